// round 1
// baseline (speedup 1.0000x reference)
#include <cuda_runtime.h>
#include <cuda_bf16.h>

// Problem constants: x [16, 1024, 256], F = 256
#define BATCH 16
#define SEQ   1024
#define FEAT  256
#define ROWS  (BATCH * SEQ)          // 16384

// Scratch (allocation-free rule: __device__ globals)
__device__ __align__(16) float g_alpha[ROWS * FEAT];
__device__ __align__(16) float g_beta [ROWS * FEAT];
__device__ __align__(16) float g_unary[ROWS * FEAT];
__device__ __align__(16) float g_att  [ROWS * FEAT];
__device__ __align__(16) float g_M    [BATCH * FEAT * FEAT];
__device__ __align__(16) float g_s    [ROWS];

// ---------------------------------------------------------------------------
// Generic tiled fp32 GEMM: C[M,N] = A ? B with fused epilogues.
//   A_KMAJ: A stored [M, K] row-major (K contiguous). else A stored [K, M] (M contiguous, i.e. A^T view)
//   B_KMAJ: B stored [N, K] row-major (C = A * B^T). else B stored [K, N] (N contiguous)
// EPI: 0 = none, 1 = +bias[n], 2 = (acc - s[r]*unary[r,n]) * (1/1024), 3 = +x[r,n]
// ---------------------------------------------------------------------------
#define BM 64
#define BN 64
#define BKT 16
#define TM 4
#define TN 4

template<bool A_KMAJ, bool B_KMAJ, int EPI>
__global__ __launch_bounds__(256)
void gemm_kernel(const float* __restrict__ A, const float* __restrict__ B,
                 float* __restrict__ C,
                 int M, int N, int K, int lda, int ldb, int ldc,
                 long sA, long sB, long sC,
                 const float* __restrict__ aux1, const float* __restrict__ aux2,
                 long sAux1, long sAux2)
{
    const int b = blockIdx.z;
    A += (long)b * sA;
    B += (long)b * sB;
    C += (long)b * sC;
    const float* x1 = aux1 ? aux1 + (long)b * sAux1 : nullptr;
    const float* x2 = aux2 ? aux2 + (long)b * sAux2 : nullptr;

    __shared__ float As[BKT][BM];
    __shared__ float Bs[BKT][BN];

    const int tid = threadIdx.x;
    const int tx = tid & 15;        // 0..15 -> column group
    const int ty = tid >> 4;        // 0..15 -> row group
    const int row0 = blockIdx.y * BM;
    const int col0 = blockIdx.x * BN;

    float acc[TM][TN];
#pragma unroll
    for (int i = 0; i < TM; i++)
#pragma unroll
        for (int j = 0; j < TN; j++) acc[i][j] = 0.0f;

    for (int k0 = 0; k0 < K; k0 += BKT) {
        // ---- load A tile ----
        if (A_KMAJ) {
            // A[M,K]: 64 rows x 16 k. thread loads one float4 along k.
            const int m  = tid >> 2;            // 0..63
            const int kq = (tid & 3) * 4;       // 0,4,8,12
            float4 v = *(const float4*)(A + (long)(row0 + m) * lda + (k0 + kq));
            As[kq + 0][m] = v.x;
            As[kq + 1][m] = v.y;
            As[kq + 2][m] = v.z;
            As[kq + 3][m] = v.w;
        } else {
            // A[K,M]: 16 k-rows x 64 cols, direct float4 store.
            const int kk = tid >> 4;            // 0..15
            const int c4 = (tid & 15) * 4;      // 0..60
            *(float4*)&As[kk][c4] =
                *(const float4*)(A + (long)(k0 + kk) * lda + (row0 + c4));
        }
        // ---- load B tile ----
        if (B_KMAJ) {
            const int n  = tid >> 2;
            const int kq = (tid & 3) * 4;
            float4 v = *(const float4*)(B + (long)(col0 + n) * ldb + (k0 + kq));
            Bs[kq + 0][n] = v.x;
            Bs[kq + 1][n] = v.y;
            Bs[kq + 2][n] = v.z;
            Bs[kq + 3][n] = v.w;
        } else {
            const int kk = tid >> 4;
            const int c4 = (tid & 15) * 4;
            *(float4*)&Bs[kk][c4] =
                *(const float4*)(B + (long)(k0 + kk) * ldb + (col0 + c4));
        }
        __syncthreads();

#pragma unroll
        for (int k = 0; k < BKT; k++) {
            float4 av4 = *(const float4*)&As[k][ty * TM];
            float4 bv4 = *(const float4*)&Bs[k][tx * TN];
            float av[TM] = {av4.x, av4.y, av4.z, av4.w};
            float bv[TN] = {bv4.x, bv4.y, bv4.z, bv4.w};
#pragma unroll
            for (int i = 0; i < TM; i++)
#pragma unroll
                for (int j = 0; j < TN; j++)
                    acc[i][j] = fmaf(av[i], bv[j], acc[i][j]);
        }
        __syncthreads();
    }

    // ---- epilogue + store (float4 per micro-row) ----
    const int c = col0 + tx * TN;
#pragma unroll
    for (int i = 0; i < TM; i++) {
        const int r = row0 + ty * TM + i;
        float o[TN];
#pragma unroll
        for (int j = 0; j < TN; j++) o[j] = acc[i][j];

        if (EPI == 1) {
#pragma unroll
            for (int j = 0; j < TN; j++) o[j] += x1[c + j];
        } else if (EPI == 2) {
            const float sv = x1[r];
            const float4 uv = *(const float4*)(x2 + (long)r * ldc + c);
            const float u[4] = {uv.x, uv.y, uv.z, uv.w};
#pragma unroll
            for (int j = 0; j < TN; j++)
                o[j] = (o[j] - sv * u[j]) * (1.0f / 1024.0f);
        } else if (EPI == 3) {
            const float4 xv = *(const float4*)(x1 + (long)r * ldc + c);
            const float xr[4] = {xv.x, xv.y, xv.z, xv.w};
#pragma unroll
            for (int j = 0; j < TN; j++) o[j] += xr[j];
        }

        float4 ov = {o[0], o[1], o[2], o[3]};
        *(float4*)(C + (long)r * ldc + c) = ov;
    }
}

// ---------------------------------------------------------------------------
// s[r] = dot(alpha[r,:], beta[r,:]) over F=256. One warp per row.
// ---------------------------------------------------------------------------
__global__ __launch_bounds__(256)
void rowdot_kernel(const float* __restrict__ a, const float* __restrict__ b,
                   float* __restrict__ s)
{
    const int row = blockIdx.x * 8 + (threadIdx.x >> 5);
    const int lane = threadIdx.x & 31;
    const float4* ar = (const float4*)(a + (long)row * FEAT);
    const float4* br = (const float4*)(b + (long)row * FEAT);
    float sum = 0.0f;
#pragma unroll
    for (int i = 0; i < 2; i++) {
        const int idx = lane + i * 32;
        float4 av = ar[idx], bv = br[idx];
        sum += av.x * bv.x + av.y * bv.y + av.z * bv.z + av.w * bv.w;
    }
#pragma unroll
    for (int o = 16; o > 0; o >>= 1)
        sum += __shfl_xor_sync(0xFFFFFFFFu, sum, o);
    if (lane == 0) s[row] = sum;
}

extern "C" void kernel_launch(void* const* d_in, const int* in_sizes, int n_in,
                              void* d_out, int out_size)
{
    const float* x       = (const float*)d_in[0];
    const float* W_alpha = (const float*)d_in[1];
    const float* W_beta  = (const float*)d_in[2];
    const float* W_unary = (const float*)d_in[3];
    const float* b_unary = (const float*)d_in[4];
    const float* W_r     = (const float*)d_in[5];
    float* out = (float*)d_out;

    float *alpha, *beta, *unary, *att, *Mm, *sv;
    cudaGetSymbolAddress((void**)&alpha, g_alpha);
    cudaGetSymbolAddress((void**)&beta,  g_beta);
    cudaGetSymbolAddress((void**)&unary, g_unary);
    cudaGetSymbolAddress((void**)&att,   g_att);
    cudaGetSymbolAddress((void**)&Mm,    g_M);
    cudaGetSymbolAddress((void**)&sv,    g_s);

    // 1) projections: alpha/beta = x @ W^T ; unary = x @ W_unary^T + b
    {
        dim3 grid(FEAT / BN, ROWS / BM, 1);
        gemm_kernel<true, true, 0><<<grid, 256>>>(
            x, W_alpha, alpha, ROWS, FEAT, FEAT, FEAT, FEAT, FEAT,
            0, 0, 0, nullptr, nullptr, 0, 0);
        gemm_kernel<true, true, 0><<<grid, 256>>>(
            x, W_beta, beta, ROWS, FEAT, FEAT, FEAT, FEAT, FEAT,
            0, 0, 0, nullptr, nullptr, 0, 0);
        gemm_kernel<true, true, 1><<<grid, 256>>>(
            x, W_unary, unary, ROWS, FEAT, FEAT, FEAT, FEAT, FEAT,
            0, 0, 0, b_unary, nullptr, 0, 0);
    }

    // 2) s[r] = alpha_r . beta_r
    rowdot_kernel<<<ROWS / 8, 256>>>(alpha, beta, sv);

    // 3) per-batch M = beta^T @ unary   ([F,F] = [N,F]^T [N,F], K = 1024)
    {
        dim3 grid(FEAT / BN, FEAT / BM, BATCH);
        gemm_kernel<false, false, 0><<<grid, 256>>>(
            beta, unary, Mm, FEAT, FEAT, SEQ, FEAT, FEAT, FEAT,
            (long)SEQ * FEAT, (long)SEQ * FEAT, (long)FEAT * FEAT,
            nullptr, nullptr, 0, 0);
    }

    // 4) per-batch att = (alpha @ M - s*unary) / 1024
    {
        dim3 grid(FEAT / BN, SEQ / BM, BATCH);
        gemm_kernel<true, false, 2><<<grid, 256>>>(
            alpha, Mm, att, SEQ, FEAT, FEAT, FEAT, FEAT, FEAT,
            (long)SEQ * FEAT, (long)FEAT * FEAT, (long)SEQ * FEAT,
            sv, unary, (long)SEQ, (long)SEQ * FEAT);
    }

    // 5) out = att @ W_r^T + x
    {
        dim3 grid(FEAT / BN, ROWS / BM, 1);
        gemm_kernel<true, true, 3><<<grid, 256>>>(
            att, W_r, out, ROWS, FEAT, FEAT, FEAT, FEAT, FEAT,
            0, 0, 0, x, nullptr, 0, 0);
    }
}

// round 2
// speedup vs baseline: 3.2925x; 3.2925x over previous
#include <cuda_runtime.h>
#include <cuda_bf16.h>
#include <cstdint>

#define BATCH 16
#define SEQ   1024
#define FEAT  256
#define ROWS  (BATCH * SEQ)     // 16384
#define PJ    768               // 3 * FEAT (alpha | beta | unary)

// ---- scratch (__device__ globals; no allocation allowed) ----
__device__ __align__(16) __nv_bfloat16 g_W   [PJ * FEAT];       // packed Wa|Wb|Wu, [g][f]
__device__ __align__(16) __nv_bfloat16 g_Wr  [FEAT * FEAT];
__device__ __align__(16) __nv_bfloat16 g_proj[ROWS * PJ];       // [r][alpha|beta|unary]
__device__ __align__(16) __nv_bfloat16 g_Mt  [BATCH * FEAT * FEAT]; // Mt[g][f] per batch
__device__ __align__(16) __nv_bfloat16 g_att [ROWS * FEAT];
__device__ float g_s[ROWS];

// ---------------------------------------------------------------------------
__device__ __forceinline__ uint32_t bf2u(__nv_bfloat162 h) {
    return *reinterpret_cast<uint32_t*>(&h);
}
__device__ __forceinline__ uint32_t smem_u32(const void* p) {
    return (uint32_t)__cvta_generic_to_shared(p);
}
__device__ __forceinline__ void mma_bf16(float c[4],
        uint32_t a0, uint32_t a1, uint32_t a2, uint32_t a3,
        uint32_t b0, uint32_t b1) {
    asm volatile(
        "mma.sync.aligned.m16n8k16.row.col.f32.bf16.bf16.f32 "
        "{%0,%1,%2,%3},{%4,%5,%6,%7},{%8,%9},{%0,%1,%2,%3};"
        : "+f"(c[0]), "+f"(c[1]), "+f"(c[2]), "+f"(c[3])
        : "r"(a0), "r"(a1), "r"(a2), "r"(a3), "r"(b0), "r"(b1));
}

// ---------------------------------------------------------------------------
// Weight pack: 3 proj weights -> g_W (bf16, [768][256]), W_r -> g_Wr
// ---------------------------------------------------------------------------
__global__ __launch_bounds__(256)
void pack_weights(const float* __restrict__ Wa, const float* __restrict__ Wb,
                  const float* __restrict__ Wu, const float* __restrict__ Wr,
                  __nv_bfloat16* __restrict__ W, __nv_bfloat16* __restrict__ Wro)
{
    int i = blockIdx.x * 256 + threadIdx.x;    // [0, 4*65536)
    int sel = i >> 16, off = i & 65535;
    const float* src = (sel == 0) ? Wa : (sel == 1) ? Wb : (sel == 2) ? Wu : Wr;
    float v = src[off];
    if (sel < 3) W[i] = __float2bfloat16(v);
    else         Wro[off] = __float2bfloat16(v);
}

// ---------------------------------------------------------------------------
// NT GEMM: C[M,N] = A[M,K] * B[N,K]^T, bf16 tensor-core, fused epilogues.
// BM=128, BN=64, BK=32, 256 threads (8 warps: 4m x 2n), warp tile 32x32.
// EPI: 0 none, 1 +bias for n>=512 (bias[n-512]), 2 (acc - s[r]*u[r,n])/1024,
//      3 +x[r,n] (fp32 out)
// ---------------------------------------------------------------------------
template<int EPI, bool A_F32, bool OUT_F32>
__global__ __launch_bounds__(256)
void gemm_nt(const void* __restrict__ Ap, int lda, long sA,
             const __nv_bfloat16* __restrict__ B, int ldb, long sB,
             void* __restrict__ Cp, int ldc, long sC, int K,
             const float* __restrict__ bias,
             const float* __restrict__ sdot, long sS,
             const __nv_bfloat16* __restrict__ U, int ldu, long sU,
             const float* __restrict__ Xres, int ldx, long sX)
{
    const int z = blockIdx.z;
    const float*         Af  = A_F32 ? (const float*)Ap + (size_t)z * sA : nullptr;
    const __nv_bfloat16* Abf = A_F32 ? nullptr : (const __nv_bfloat16*)Ap + (size_t)z * sA;
    const __nv_bfloat16* Bz  = B + (size_t)z * sB;

    __shared__ __align__(16) __nv_bfloat16 As[128][40];   // pad 8: conflict-free frags
    __shared__ __align__(16) __nv_bfloat16 Bs[64][40];

    const int tid  = threadIdx.x;
    const int lane = tid & 31, warp = tid >> 5;
    const int wm = warp >> 1, wn = warp & 1;
    const int g = lane >> 2, t = lane & 3;
    const int row0 = blockIdx.y * 128, col0 = blockIdx.x * 64;

    float acc[2][4][4] = {};

    for (int k0 = 0; k0 < K; k0 += 32) {
        // ---- stage A: 128 x 32 ----
        {
            const int r = tid >> 1, seg = tid & 1;
            if (A_F32) {
                const float* src = Af + (size_t)(row0 + r) * lda + k0 + seg * 16;
                float4 v0 = ((const float4*)src)[0];
                float4 v1 = ((const float4*)src)[1];
                float4 v2 = ((const float4*)src)[2];
                float4 v3 = ((const float4*)src)[3];
                uint4 p0 = make_uint4(
                    bf2u(__floats2bfloat162_rn(v0.x, v0.y)),
                    bf2u(__floats2bfloat162_rn(v0.z, v0.w)),
                    bf2u(__floats2bfloat162_rn(v1.x, v1.y)),
                    bf2u(__floats2bfloat162_rn(v1.z, v1.w)));
                uint4 p1 = make_uint4(
                    bf2u(__floats2bfloat162_rn(v2.x, v2.y)),
                    bf2u(__floats2bfloat162_rn(v2.z, v2.w)),
                    bf2u(__floats2bfloat162_rn(v3.x, v3.y)),
                    bf2u(__floats2bfloat162_rn(v3.z, v3.w)));
                *(uint4*)&As[r][seg * 16]     = p0;
                *(uint4*)&As[r][seg * 16 + 8] = p1;
            } else {
                const __nv_bfloat16* src = Abf + (size_t)(row0 + r) * lda + k0 + seg * 16;
                uint4 q0 = ((const uint4*)src)[0];
                uint4 q1 = ((const uint4*)src)[1];
                *(uint4*)&As[r][seg * 16]     = q0;
                *(uint4*)&As[r][seg * 16 + 8] = q1;
            }
        }
        // ---- stage B: 64 x 32 (always bf16) ----
        {
            const int r = tid >> 2, seg = tid & 3;
            *(uint4*)&Bs[r][seg * 8] =
                *(const uint4*)(Bz + (size_t)(col0 + r) * ldb + k0 + seg * 8);
        }
        __syncthreads();

        const uint32_t* Au = (const uint32_t*)&As[0][0];   // row stride 20 u32
        const uint32_t* Bu = (const uint32_t*)&Bs[0][0];
#pragma unroll
        for (int kc = 0; kc < 2; kc++) {
            uint32_t a[2][4];
#pragma unroll
            for (int i = 0; i < 2; i++) {
                const int r = wm * 32 + i * 16;
                a[i][0] = Au[(r + g)     * 20 + kc * 8 + t];
                a[i][1] = Au[(r + g + 8) * 20 + kc * 8 + t];
                a[i][2] = Au[(r + g)     * 20 + kc * 8 + t + 4];
                a[i][3] = Au[(r + g + 8) * 20 + kc * 8 + t + 4];
            }
#pragma unroll
            for (int j = 0; j < 4; j++) {
                const int c = wn * 32 + j * 8;
                uint32_t b0 = Bu[(c + g) * 20 + kc * 8 + t];
                uint32_t b1 = Bu[(c + g) * 20 + kc * 8 + t + 4];
#pragma unroll
                for (int i = 0; i < 2; i++)
                    mma_bf16(acc[i][j], a[i][0], a[i][1], a[i][2], a[i][3], b0, b1);
            }
        }
        __syncthreads();
    }

    // ---- epilogue ----
    const float invN = 1.0f / 1024.0f;
    const float* sd           = (EPI == 2) ? sdot + (size_t)z * sS : nullptr;
    const __nv_bfloat16* Uz   = (EPI == 2) ? U + (size_t)z * sU : nullptr;
    const float* Xz           = (EPI == 3) ? Xres + (size_t)z * sX : nullptr;
    float*          Cf = OUT_F32 ? (float*)Cp + (size_t)z * sC : nullptr;
    __nv_bfloat16*  Cb = OUT_F32 ? nullptr : (__nv_bfloat16*)Cp + (size_t)z * sC;

#pragma unroll
    for (int i = 0; i < 2; i++) {
        const int rb = row0 + wm * 32 + i * 16 + g;   // rows rb, rb+8
#pragma unroll
        for (int j = 0; j < 4; j++) {
            const int c = col0 + wn * 32 + j * 8 + t * 2;
            float v00 = acc[i][j][0], v01 = acc[i][j][1];
            float v10 = acc[i][j][2], v11 = acc[i][j][3];
            if (EPI == 1) {
                if (c >= 512) {
                    float b0 = bias[c - 512], b1 = bias[c - 511];
                    v00 += b0; v01 += b1; v10 += b0; v11 += b1;
                }
            } else if (EPI == 2) {
                float s0 = sd[rb], s1 = sd[rb + 8];
                __nv_bfloat162 u0 = *(const __nv_bfloat162*)(Uz + (size_t)rb * ldu + c);
                __nv_bfloat162 u1 = *(const __nv_bfloat162*)(Uz + (size_t)(rb + 8) * ldu + c);
                float2 fu0 = __bfloat1622float2(u0);
                float2 fu1 = __bfloat1622float2(u1);
                v00 = (v00 - s0 * fu0.x) * invN;
                v01 = (v01 - s0 * fu0.y) * invN;
                v10 = (v10 - s1 * fu1.x) * invN;
                v11 = (v11 - s1 * fu1.y) * invN;
            } else if (EPI == 3) {
                float2 x0 = *(const float2*)(Xz + (size_t)rb * ldx + c);
                float2 x1 = *(const float2*)(Xz + (size_t)(rb + 8) * ldx + c);
                v00 += x0.x; v01 += x0.y; v10 += x1.x; v11 += x1.y;
            }
            if (OUT_F32) {
                *(float2*)(Cf + (size_t)rb * ldc + c)       = make_float2(v00, v01);
                *(float2*)(Cf + (size_t)(rb + 8) * ldc + c) = make_float2(v10, v11);
            } else {
                *(__nv_bfloat162*)(Cb + (size_t)rb * ldc + c)       = __floats2bfloat162_rn(v00, v01);
                *(__nv_bfloat162*)(Cb + (size_t)(rb + 8) * ldc + c) = __floats2bfloat162_rn(v10, v11);
            }
        }
    }
}

// ---------------------------------------------------------------------------
// TT GEMM (for Mt = unary^T * beta per batch): operands stored [K][*].
// C[M,N] = sum_k A[k][m] * B[k][n].  BM=64, BN=64, BK=32, 256 thr,
// warps 2m x 4n (warp tile 32x16). ldmatrix.trans for both fragments.
// ---------------------------------------------------------------------------
__global__ __launch_bounds__(256)
void gemm_tt(const __nv_bfloat16* __restrict__ A, int lda, long sA,
             const __nv_bfloat16* __restrict__ B, int ldb, long sB,
             __nv_bfloat16* __restrict__ C, int ldc, long sC, int K)
{
    const int z = blockIdx.z;
    A += (size_t)z * sA; B += (size_t)z * sB; C += (size_t)z * sC;

    __shared__ __align__(16) __nv_bfloat16 SA[32][72];   // [k][m], pad 8
    __shared__ __align__(16) __nv_bfloat16 SB[32][72];   // [k][n]

    const int tid = threadIdx.x, lane = tid & 31, warp = tid >> 5;
    const int wm = warp >> 2, wn = warp & 3;
    const int m0 = blockIdx.y * 64, n0 = blockIdx.x * 64;

    float acc[2][2][4] = {};

    // ldmatrix lane->address mapping (element offsets within the k16 tile)
    const int arow = ((lane >> 4) << 3) + (lane & 7);    // k row 0..15
    const int acol = ((lane >> 3) & 1) << 3;             // m offset 0/8
    const int brow = (((lane >> 3) & 1) << 3) + (lane & 7);

    for (int k0 = 0; k0 < K; k0 += 32) {
        const int r = tid >> 3, seg = tid & 7;           // 32 rows x 8 segs
        *(uint4*)&SA[r][seg * 8] = *(const uint4*)(A + (size_t)(k0 + r) * lda + m0 + seg * 8);
        *(uint4*)&SB[r][seg * 8] = *(const uint4*)(B + (size_t)(k0 + r) * ldb + n0 + seg * 8);
        __syncthreads();

#pragma unroll
        for (int kc = 0; kc < 2; kc++) {
            uint32_t a[2][4], b[2][2];
#pragma unroll
            for (int i = 0; i < 2; i++) {
                const int mb = wm * 32 + i * 16;
                uint32_t addr = smem_u32(&SA[kc * 16 + arow][mb + acol]);
                asm volatile(
                    "ldmatrix.sync.aligned.m8n8.x4.trans.shared.b16 {%0,%1,%2,%3},[%4];"
                    : "=r"(a[i][0]), "=r"(a[i][1]), "=r"(a[i][2]), "=r"(a[i][3])
                    : "r"(addr));
            }
#pragma unroll
            for (int j = 0; j < 2; j++) {
                const int nb = wn * 16 + j * 8;
                uint32_t addr = smem_u32(&SB[kc * 16 + brow][nb]);
                asm volatile(
                    "ldmatrix.sync.aligned.m8n8.x2.trans.shared.b16 {%0,%1},[%2];"
                    : "=r"(b[j][0]), "=r"(b[j][1])
                    : "r"(addr));
            }
#pragma unroll
            for (int i = 0; i < 2; i++)
#pragma unroll
                for (int j = 0; j < 2; j++)
                    mma_bf16(acc[i][j], a[i][0], a[i][1], a[i][2], a[i][3],
                             b[j][0], b[j][1]);
        }
        __syncthreads();
    }

    const int g = lane >> 2, t = lane & 3;
#pragma unroll
    for (int i = 0; i < 2; i++) {
        const int rb = m0 + wm * 32 + i * 16 + g;
#pragma unroll
        for (int j = 0; j < 2; j++) {
            const int c = n0 + wn * 16 + j * 8 + t * 2;
            *(__nv_bfloat162*)(C + (size_t)rb * ldc + c)       = __floats2bfloat162_rn(acc[i][j][0], acc[i][j][1]);
            *(__nv_bfloat162*)(C + (size_t)(rb + 8) * ldc + c) = __floats2bfloat162_rn(acc[i][j][2], acc[i][j][3]);
        }
    }
}

// ---------------------------------------------------------------------------
// s[r] = dot(alpha[r,:], beta[r,:]) from bf16 proj (ld = 768). Warp per row.
// ---------------------------------------------------------------------------
__global__ __launch_bounds__(256)
void rowdot(const __nv_bfloat16* __restrict__ proj, float* __restrict__ s)
{
    const int row  = blockIdx.x * 8 + (threadIdx.x >> 5);
    const int lane = threadIdx.x & 31;
    const __nv_bfloat16* pa = proj + (size_t)row * PJ + lane * 8;
    uint4 va = *(const uint4*)pa;
    uint4 vb = *(const uint4*)(pa + FEAT);
    const __nv_bfloat162* ha = (const __nv_bfloat162*)&va;
    const __nv_bfloat162* hb = (const __nv_bfloat162*)&vb;
    float sum = 0.0f;
#pragma unroll
    for (int i = 0; i < 4; i++) {
        float2 fa = __bfloat1622float2(ha[i]);
        float2 fb = __bfloat1622float2(hb[i]);
        sum += fa.x * fb.x + fa.y * fb.y;
    }
#pragma unroll
    for (int o = 16; o > 0; o >>= 1)
        sum += __shfl_xor_sync(0xFFFFFFFFu, sum, o);
    if (lane == 0) s[row] = sum;
}

// ---------------------------------------------------------------------------
extern "C" void kernel_launch(void* const* d_in, const int* in_sizes, int n_in,
                              void* d_out, int out_size)
{
    const float* x  = (const float*)d_in[0];
    const float* Wa = (const float*)d_in[1];
    const float* Wb = (const float*)d_in[2];
    const float* Wu = (const float*)d_in[3];
    const float* bu = (const float*)d_in[4];
    const float* Wr = (const float*)d_in[5];
    float* out = (float*)d_out;

    __nv_bfloat16 *W, *Wr2, *proj, *Mt, *att;
    float* s;
    cudaGetSymbolAddress((void**)&W,    g_W);
    cudaGetSymbolAddress((void**)&Wr2,  g_Wr);
    cudaGetSymbolAddress((void**)&proj, g_proj);
    cudaGetSymbolAddress((void**)&Mt,   g_Mt);
    cudaGetSymbolAddress((void**)&att,  g_att);
    cudaGetSymbolAddress((void**)&s,    g_s);

    // 0) pack weights to bf16
    pack_weights<<<1024, 256>>>(Wa, Wb, Wu, Wr, W, Wr2);

    // 1) fused projections: proj = x @ [Wa|Wb|Wu]^T (+bias on unary cols)
    gemm_nt<1, true, false><<<dim3(PJ / 64, ROWS / 128, 1), 256>>>(
        x, FEAT, 0, W, FEAT, 0, proj, PJ, 0, FEAT,
        bu, nullptr, 0, nullptr, 0, 0, nullptr, 0, 0);

    // 2) s[r] = alpha_r . beta_r
    rowdot<<<ROWS / 8, 256>>>(proj, s);

    // 3) per-batch Mt[g,f] = sum_n unary[n,g] * beta[n,f]
    gemm_tt<<<dim3(FEAT / 64, FEAT / 64, BATCH), 256>>>(
        proj + 512, PJ, (long)SEQ * PJ,
        proj + 256, PJ, (long)SEQ * PJ,
        Mt, FEAT, (long)FEAT * FEAT, SEQ);

    // 4) per-batch att = (alpha @ Mt^T - s*unary) / 1024
    gemm_nt<2, false, false><<<dim3(FEAT / 64, SEQ / 128, BATCH), 256>>>(
        proj, PJ, (long)SEQ * PJ,
        Mt, FEAT, (long)FEAT * FEAT,
        att, FEAT, (long)SEQ * FEAT, FEAT,
        nullptr, s, (long)SEQ, proj + 512, PJ, (long)SEQ * PJ, nullptr, 0, 0);

    // 5) out = att @ W_r^T + x  (fp32 out)
    gemm_nt<3, false, true><<<dim3(FEAT / 64, ROWS / 128, 1), 256>>>(
        att, FEAT, 0, Wr2, FEAT, 0, out, FEAT, 0, FEAT,
        nullptr, nullptr, 0, nullptr, 0, 0, x, FEAT, 0);
}

// round 3
// speedup vs baseline: 3.7177x; 1.1291x over previous
#include <cuda_runtime.h>
#include <cuda_bf16.h>
#include <cstdint>

#define BATCH 16
#define SEQ   1024
#define FEAT  256
#define ROWS  (BATCH * SEQ)     // 16384
#define PJ    768               // 3 * FEAT (alpha | beta | unary)

// ---- scratch (__device__ globals; no allocation allowed) ----
__device__ __align__(16) __nv_bfloat16 g_W   [PJ * FEAT];       // packed Wa|Wb|Wu, [g][f]
__device__ __align__(16) __nv_bfloat16 g_Wr  [FEAT * FEAT];
__device__ __align__(16) __nv_bfloat16 g_xb  [ROWS * FEAT];     // x in bf16
__device__ __align__(16) __nv_bfloat16 g_proj[ROWS * PJ];       // [r][alpha|beta|unary]
__device__ __align__(16) __nv_bfloat16 g_Mt  [BATCH * FEAT * FEAT]; // Mt[g][f] per batch
__device__ __align__(16) __nv_bfloat16 g_att [ROWS * FEAT];
__device__ float g_s[ROWS];

// ---------------------------------------------------------------------------
__device__ __forceinline__ uint32_t smem_u32(const void* p) {
    return (uint32_t)__cvta_generic_to_shared(p);
}
__device__ __forceinline__ void cp16(void* s, const void* g) {
    asm volatile("cp.async.ca.shared.global [%0], [%1], 16;\n"
                 :: "r"(smem_u32(s)), "l"(g));
}
__device__ __forceinline__ void cp_commit() {
    asm volatile("cp.async.commit_group;\n");
}
__device__ __forceinline__ void cp_wait1() {
    asm volatile("cp.async.wait_group 1;\n");
}
__device__ __forceinline__ void mma_bf16(float c[4],
        uint32_t a0, uint32_t a1, uint32_t a2, uint32_t a3,
        uint32_t b0, uint32_t b1) {
    asm volatile(
        "mma.sync.aligned.m16n8k16.row.col.f32.bf16.bf16.f32 "
        "{%0,%1,%2,%3},{%4,%5,%6,%7},{%8,%9},{%0,%1,%2,%3};"
        : "+f"(c[0]), "+f"(c[1]), "+f"(c[2]), "+f"(c[3])
        : "r"(a0), "r"(a1), "r"(a2), "r"(a3), "r"(b0), "r"(b1));
}

// ---------------------------------------------------------------------------
// Weight pack: 3 proj weights -> g_W (bf16, [768][256]), W_r -> g_Wr
// ---------------------------------------------------------------------------
__global__ __launch_bounds__(256)
void pack_weights(const float* __restrict__ Wa, const float* __restrict__ Wb,
                  const float* __restrict__ Wu, const float* __restrict__ Wr,
                  __nv_bfloat16* __restrict__ W, __nv_bfloat16* __restrict__ Wro)
{
    int i = blockIdx.x * 256 + threadIdx.x;    // [0, 4*65536)
    int sel = i >> 16, off = i & 65535;
    const float* src = (sel == 0) ? Wa : (sel == 1) ? Wb : (sel == 2) ? Wu : Wr;
    float v = src[off];
    if (sel < 3) W[i] = __float2bfloat16(v);
    else         Wro[off] = __float2bfloat16(v);
}

// x (fp32) -> xb (bf16), 4 elems / thread
__global__ __launch_bounds__(256)
void convert_x(const float* __restrict__ x, __nv_bfloat16* __restrict__ xb)
{
    int i = (blockIdx.x * 256 + threadIdx.x) * 4;
    float4 v = *(const float4*)(x + i);
    __nv_bfloat162 p0 = __floats2bfloat162_rn(v.x, v.y);
    __nv_bfloat162 p1 = __floats2bfloat162_rn(v.z, v.w);
    uint2 o = make_uint2(*(uint32_t*)&p0, *(uint32_t*)&p1);
    *(uint2*)(xb + i) = o;
}

// ---------------------------------------------------------------------------
// NT GEMM: C[M,N] = A[M,K] * B[N,K]^T, bf16, 3-stage cp.async pipeline.
// BM=128, BN=64, BK=32, 256 threads (8 warps: 4m x 2n), warp tile 32x32.
// EPI: 0 none, 1 +bias for n>=512 (bias[n-512]), 2 (acc - s[r]*u[r,n])/1024,
//      3 +x[r,n] (fp32 out)
// ---------------------------------------------------------------------------
template<int EPI, bool OUT_F32>
__global__ __launch_bounds__(256)
void gemm_nt(const __nv_bfloat16* __restrict__ A, int lda, long sA,
             const __nv_bfloat16* __restrict__ B, int ldb, long sB,
             void* __restrict__ Cp, int ldc, long sC, int K,
             const float* __restrict__ bias,
             const float* __restrict__ sdot, long sS,
             const __nv_bfloat16* __restrict__ U, int ldu, long sU,
             const float* __restrict__ Xres, int ldx, long sX)
{
    const int z = blockIdx.z;
    A += (size_t)z * sA;
    B += (size_t)z * sB;

    __shared__ __align__(16) __nv_bfloat16 As[3][128][40];  // pad 8
    __shared__ __align__(16) __nv_bfloat16 Bs[3][64][40];

    const int tid  = threadIdx.x;
    const int lane = tid & 31, warp = tid >> 5;
    const int wm = warp >> 1, wn = warp & 1;
    const int g = lane >> 2, t = lane & 3;
    const int row0 = blockIdx.y * 128, col0 = blockIdx.x * 64;

    const int ar = tid >> 1, ac = (tid & 1) * 16;     // A: 128 rows, 2 half-rows
    const int br = tid >> 2, bc = (tid & 3) * 8;      // B: 64 rows, 4 segs

    float acc[2][4][4] = {};
    const int kIters = K / 32;

    const __nv_bfloat16* aSrc = A + (size_t)(row0 + ar) * lda + ac;
    const __nv_bfloat16* bSrc = B + (size_t)(col0 + br) * ldb + bc;

#pragma unroll
    for (int s = 0; s < 2; s++) {
        if (s < kIters) {
            cp16(&As[s][ar][ac],     aSrc + s * 32);
            cp16(&As[s][ar][ac + 8], aSrc + s * 32 + 8);
            cp16(&Bs[s][br][bc],     bSrc + s * 32);
        }
        cp_commit();
    }

    for (int it = 0; it < kIters; it++) {
        cp_wait1();
        __syncthreads();
        if (it + 2 < kIters) {
            const int st = (it + 2) % 3;
            cp16(&As[st][ar][ac],     aSrc + (it + 2) * 32);
            cp16(&As[st][ar][ac + 8], aSrc + (it + 2) * 32 + 8);
            cp16(&Bs[st][br][bc],     bSrc + (it + 2) * 32);
        }
        cp_commit();

        const int st = it % 3;
        const uint32_t* Au = (const uint32_t*)&As[st][0][0];  // row stride 20 u32
        const uint32_t* Bu = (const uint32_t*)&Bs[st][0][0];
#pragma unroll
        for (int kc = 0; kc < 2; kc++) {
            uint32_t a[2][4];
#pragma unroll
            for (int i = 0; i < 2; i++) {
                const int r = wm * 32 + i * 16;
                a[i][0] = Au[(r + g)     * 20 + kc * 8 + t];
                a[i][1] = Au[(r + g + 8) * 20 + kc * 8 + t];
                a[i][2] = Au[(r + g)     * 20 + kc * 8 + t + 4];
                a[i][3] = Au[(r + g + 8) * 20 + kc * 8 + t + 4];
            }
#pragma unroll
            for (int j = 0; j < 4; j++) {
                const int c = wn * 32 + j * 8;
                uint32_t b0 = Bu[(c + g) * 20 + kc * 8 + t];
                uint32_t b1 = Bu[(c + g) * 20 + kc * 8 + t + 4];
#pragma unroll
                for (int i = 0; i < 2; i++)
                    mma_bf16(acc[i][j], a[i][0], a[i][1], a[i][2], a[i][3], b0, b1);
            }
        }
    }

    // ---- epilogue ----
    const float invN = 1.0f / 1024.0f;
    const float* sd           = (EPI == 2) ? sdot + (size_t)z * sS : nullptr;
    const __nv_bfloat16* Uz   = (EPI == 2) ? U + (size_t)z * sU : nullptr;
    const float* Xz           = (EPI == 3) ? Xres + (size_t)z * sX : nullptr;
    float*          Cf = OUT_F32 ? (float*)Cp + (size_t)z * sC : nullptr;
    __nv_bfloat16*  Cb = OUT_F32 ? nullptr : (__nv_bfloat16*)Cp + (size_t)z * sC;

#pragma unroll
    for (int i = 0; i < 2; i++) {
        const int rb = row0 + wm * 32 + i * 16 + g;   // rows rb, rb+8
#pragma unroll
        for (int j = 0; j < 4; j++) {
            const int c = col0 + wn * 32 + j * 8 + t * 2;
            float v00 = acc[i][j][0], v01 = acc[i][j][1];
            float v10 = acc[i][j][2], v11 = acc[i][j][3];
            if (EPI == 1) {
                if (c >= 512) {
                    float b0 = bias[c - 512], b1 = bias[c - 511];
                    v00 += b0; v01 += b1; v10 += b0; v11 += b1;
                }
            } else if (EPI == 2) {
                float s0 = sd[rb], s1 = sd[rb + 8];
                __nv_bfloat162 u0 = *(const __nv_bfloat162*)(Uz + (size_t)rb * ldu + c);
                __nv_bfloat162 u1 = *(const __nv_bfloat162*)(Uz + (size_t)(rb + 8) * ldu + c);
                float2 fu0 = __bfloat1622float2(u0);
                float2 fu1 = __bfloat1622float2(u1);
                v00 = (v00 - s0 * fu0.x) * invN;
                v01 = (v01 - s0 * fu0.y) * invN;
                v10 = (v10 - s1 * fu1.x) * invN;
                v11 = (v11 - s1 * fu1.y) * invN;
            } else if (EPI == 3) {
                float2 x0 = *(const float2*)(Xz + (size_t)rb * ldx + c);
                float2 x1 = *(const float2*)(Xz + (size_t)(rb + 8) * ldx + c);
                v00 += x0.x; v01 += x0.y; v10 += x1.x; v11 += x1.y;
            }
            if (OUT_F32) {
                *(float2*)(Cf + (size_t)rb * ldc + c)       = make_float2(v00, v01);
                *(float2*)(Cf + (size_t)(rb + 8) * ldc + c) = make_float2(v10, v11);
            } else {
                *(__nv_bfloat162*)(Cb + (size_t)rb * ldc + c)       = __floats2bfloat162_rn(v00, v01);
                *(__nv_bfloat162*)(Cb + (size_t)(rb + 8) * ldc + c) = __floats2bfloat162_rn(v10, v11);
            }
        }
    }
}

// ---------------------------------------------------------------------------
// TT GEMM (Mt = unary^T * beta per batch): operands stored [K][*].
// C[M,N] = sum_k A[k][m] * B[k][n]. BM=64, BN=64, BK=32, 256 thr,
// warps 2m x 4n (warp tile 32x16), ldmatrix.trans, 3-stage cp.async.
// ---------------------------------------------------------------------------
__global__ __launch_bounds__(256)
void gemm_tt(const __nv_bfloat16* __restrict__ A, int lda, long sA,
             const __nv_bfloat16* __restrict__ B, int ldb, long sB,
             __nv_bfloat16* __restrict__ C, int ldc, long sC, int K)
{
    const int z = blockIdx.z;
    A += (size_t)z * sA; B += (size_t)z * sB; C += (size_t)z * sC;

    __shared__ __align__(16) __nv_bfloat16 SA[3][32][72];   // [k][m], pad 8
    __shared__ __align__(16) __nv_bfloat16 SB[3][32][72];   // [k][n]

    const int tid = threadIdx.x, lane = tid & 31, warp = tid >> 5;
    const int wm = warp >> 2, wn = warp & 3;
    const int m0 = blockIdx.y * 64, n0 = blockIdx.x * 64;

    const int lr = tid >> 3, lc = (tid & 7) * 8;            // 32 rows x 8 segs

    float acc[2][2][4] = {};

    const int arow = ((lane >> 4) << 3) + (lane & 7);       // ldmatrix addressing
    const int acol = ((lane >> 3) & 1) << 3;
    const int brow = (((lane >> 3) & 1) << 3) + (lane & 7);

    const __nv_bfloat16* aSrc = A + (size_t)lr * lda + m0 + lc;
    const __nv_bfloat16* bSrc = B + (size_t)lr * ldb + n0 + lc;
    const int kIters = K / 32;

#pragma unroll
    for (int s = 0; s < 2; s++) {
        if (s < kIters) {
            cp16(&SA[s][lr][lc], aSrc + (size_t)(s * 32) * lda);
            cp16(&SB[s][lr][lc], bSrc + (size_t)(s * 32) * ldb);
        }
        cp_commit();
    }

    for (int it = 0; it < kIters; it++) {
        cp_wait1();
        __syncthreads();
        if (it + 2 < kIters) {
            const int st = (it + 2) % 3;
            cp16(&SA[st][lr][lc], aSrc + (size_t)((it + 2) * 32) * lda);
            cp16(&SB[st][lr][lc], bSrc + (size_t)((it + 2) * 32) * ldb);
        }
        cp_commit();

        const int st = it % 3;
#pragma unroll
        for (int kc = 0; kc < 2; kc++) {
            uint32_t a[2][4], b[2][2];
#pragma unroll
            for (int i = 0; i < 2; i++) {
                const int mb = wm * 32 + i * 16;
                uint32_t addr = smem_u32(&SA[st][kc * 16 + arow][mb + acol]);
                asm volatile(
                    "ldmatrix.sync.aligned.m8n8.x4.trans.shared.b16 {%0,%1,%2,%3},[%4];"
                    : "=r"(a[i][0]), "=r"(a[i][1]), "=r"(a[i][2]), "=r"(a[i][3])
                    : "r"(addr));
            }
#pragma unroll
            for (int j = 0; j < 2; j++) {
                const int nb = wn * 16 + j * 8;
                uint32_t addr = smem_u32(&SB[st][kc * 16 + brow][nb]);
                asm volatile(
                    "ldmatrix.sync.aligned.m8n8.x2.trans.shared.b16 {%0,%1},[%2];"
                    : "=r"(b[j][0]), "=r"(b[j][1])
                    : "r"(addr));
            }
#pragma unroll
            for (int i = 0; i < 2; i++)
#pragma unroll
                for (int j = 0; j < 2; j++)
                    mma_bf16(acc[i][j], a[i][0], a[i][1], a[i][2], a[i][3],
                             b[j][0], b[j][1]);
        }
    }

    const int g = lane >> 2, t = lane & 3;
#pragma unroll
    for (int i = 0; i < 2; i++) {
        const int rb = m0 + wm * 32 + i * 16 + g;
#pragma unroll
        for (int j = 0; j < 2; j++) {
            const int c = n0 + wn * 16 + j * 8 + t * 2;
            *(__nv_bfloat162*)(C + (size_t)rb * ldc + c)       = __floats2bfloat162_rn(acc[i][j][0], acc[i][j][1]);
            *(__nv_bfloat162*)(C + (size_t)(rb + 8) * ldc + c) = __floats2bfloat162_rn(acc[i][j][2], acc[i][j][3]);
        }
    }
}

// ---------------------------------------------------------------------------
// s[r] = dot(alpha[r,:], beta[r,:]) from bf16 proj (ld = 768). Warp per row.
// ---------------------------------------------------------------------------
__global__ __launch_bounds__(256)
void rowdot(const __nv_bfloat16* __restrict__ proj, float* __restrict__ s)
{
    const int row  = blockIdx.x * 8 + (threadIdx.x >> 5);
    const int lane = threadIdx.x & 31;
    const __nv_bfloat16* pa = proj + (size_t)row * PJ + lane * 8;
    uint4 va = *(const uint4*)pa;
    uint4 vb = *(const uint4*)(pa + FEAT);
    const __nv_bfloat162* ha = (const __nv_bfloat162*)&va;
    const __nv_bfloat162* hb = (const __nv_bfloat162*)&vb;
    float sum = 0.0f;
#pragma unroll
    for (int i = 0; i < 4; i++) {
        float2 fa = __bfloat1622float2(ha[i]);
        float2 fb = __bfloat1622float2(hb[i]);
        sum += fa.x * fb.x + fa.y * fb.y;
    }
#pragma unroll
    for (int o = 16; o > 0; o >>= 1)
        sum += __shfl_xor_sync(0xFFFFFFFFu, sum, o);
    if (lane == 0) s[row] = sum;
}

// ---------------------------------------------------------------------------
extern "C" void kernel_launch(void* const* d_in, const int* in_sizes, int n_in,
                              void* d_out, int out_size)
{
    const float* x  = (const float*)d_in[0];
    const float* Wa = (const float*)d_in[1];
    const float* Wb = (const float*)d_in[2];
    const float* Wu = (const float*)d_in[3];
    const float* bu = (const float*)d_in[4];
    const float* Wr = (const float*)d_in[5];
    float* out = (float*)d_out;

    __nv_bfloat16 *W, *Wr2, *xb, *proj, *Mt, *att;
    float* s;
    cudaGetSymbolAddress((void**)&W,    g_W);
    cudaGetSymbolAddress((void**)&Wr2,  g_Wr);
    cudaGetSymbolAddress((void**)&xb,   g_xb);
    cudaGetSymbolAddress((void**)&proj, g_proj);
    cudaGetSymbolAddress((void**)&Mt,   g_Mt);
    cudaGetSymbolAddress((void**)&att,  g_att);
    cudaGetSymbolAddress((void**)&s,    g_s);

    // 0) pack weights + convert x to bf16
    pack_weights<<<1024, 256>>>(Wa, Wb, Wu, Wr, W, Wr2);
    convert_x<<<ROWS * FEAT / 1024, 256>>>(x, xb);

    // 1) fused projections: proj = x @ [Wa|Wb|Wu]^T (+bias on unary cols)
    gemm_nt<1, false><<<dim3(PJ / 64, ROWS / 128, 1), 256>>>(
        xb, FEAT, 0, W, FEAT, 0, proj, PJ, 0, FEAT,
        bu, nullptr, 0, nullptr, 0, 0, nullptr, 0, 0);

    // 2) s[r] = alpha_r . beta_r
    rowdot<<<ROWS / 8, 256>>>(proj, s);

    // 3) per-batch Mt[g,f] = sum_n unary[n,g] * beta[n,f]
    gemm_tt<<<dim3(FEAT / 64, FEAT / 64, BATCH), 256>>>(
        proj + 512, PJ, (long)SEQ * PJ,
        proj + 256, PJ, (long)SEQ * PJ,
        Mt, FEAT, (long)FEAT * FEAT, SEQ);

    // 4) per-batch att = (alpha @ Mt^T - s*unary) / 1024
    gemm_nt<2, false><<<dim3(FEAT / 64, SEQ / 128, BATCH), 256>>>(
        proj, PJ, (long)SEQ * PJ,
        Mt, FEAT, (long)FEAT * FEAT,
        att, FEAT, (long)SEQ * FEAT, FEAT,
        nullptr, s, (long)SEQ, proj + 512, PJ, (long)SEQ * PJ, nullptr, 0, 0);

    // 5) out = att @ W_r^T + x  (fp32 out)
    gemm_nt<3, true><<<dim3(FEAT / 64, ROWS / 128, 1), 256>>>(
        att, FEAT, 0, Wr2, FEAT, 0, out, FEAT, 0, FEAT,
        nullptr, nullptr, 0, nullptr, 0, 0, x, FEAT, 0);
}

// round 4
// speedup vs baseline: 4.3972x; 1.1828x over previous
#include <cuda_runtime.h>
#include <cuda_bf16.h>
#include <cstdint>

#define BATCH 16
#define SEQ   1024
#define FEAT  256
#define ROWS  (BATCH * SEQ)     // 16384
#define PJ    768               // 3 * FEAT (alpha | beta | unary)

// ---- scratch (__device__ globals; no allocation allowed) ----
__device__ __align__(16) __nv_bfloat16 g_W   [PJ * FEAT];       // packed Wa|Wb|Wu
__device__ __align__(16) __nv_bfloat16 g_Wr  [FEAT * FEAT];
__device__ __align__(16) __nv_bfloat16 g_xb  [ROWS * FEAT];     // x in bf16
__device__ __align__(16) __nv_bfloat16 g_proj[ROWS * PJ];       // [r][alpha|beta|unary]
__device__ __align__(16) __nv_bfloat16 g_Mt  [BATCH * FEAT * FEAT];
__device__ __align__(16) __nv_bfloat16 g_att [ROWS * FEAT];
__device__ float g_s[ROWS];

// ---------------------------------------------------------------------------
__device__ __forceinline__ uint32_t smem_u32(const void* p) {
    return (uint32_t)__cvta_generic_to_shared(p);
}
__device__ __forceinline__ void cp16(void* s, const void* g) {
    asm volatile("cp.async.ca.shared.global [%0], [%1], 16;\n"
                 :: "r"(smem_u32(s)), "l"(g));
}
__device__ __forceinline__ void cp_commit() {
    asm volatile("cp.async.commit_group;\n");
}
__device__ __forceinline__ void cp_wait1() {
    asm volatile("cp.async.wait_group 1;\n");
}
__device__ __forceinline__ void mma_bf16(float c[4],
        uint32_t a0, uint32_t a1, uint32_t a2, uint32_t a3,
        uint32_t b0, uint32_t b1) {
    asm volatile(
        "mma.sync.aligned.m16n8k16.row.col.f32.bf16.bf16.f32 "
        "{%0,%1,%2,%3},{%4,%5,%6,%7},{%8,%9},{%0,%1,%2,%3};"
        : "+f"(c[0]), "+f"(c[1]), "+f"(c[2]), "+f"(c[3])
        : "r"(a0), "r"(a1), "r"(a2), "r"(a3), "r"(b0), "r"(b1));
}
__device__ __forceinline__ void ldm4(uint32_t r[4], const void* p) {
    asm volatile(
        "ldmatrix.sync.aligned.m8n8.x4.shared.b16 {%0,%1,%2,%3},[%4];"
        : "=r"(r[0]), "=r"(r[1]), "=r"(r[2]), "=r"(r[3])
        : "r"(smem_u32(p)));
}

// ---------------------------------------------------------------------------
__global__ __launch_bounds__(256)
void pack_weights(const float* __restrict__ Wa, const float* __restrict__ Wb,
                  const float* __restrict__ Wu, const float* __restrict__ Wr,
                  __nv_bfloat16* __restrict__ W, __nv_bfloat16* __restrict__ Wro)
{
    int i = blockIdx.x * 256 + threadIdx.x;
    int sel = i >> 16, off = i & 65535;
    const float* src = (sel == 0) ? Wa : (sel == 1) ? Wb : (sel == 2) ? Wu : Wr;
    float v = src[off];
    if (sel < 3) W[i] = __float2bfloat16(v);
    else         Wro[off] = __float2bfloat16(v);
}

__global__ __launch_bounds__(256)
void convert_x(const float* __restrict__ x, __nv_bfloat16* __restrict__ xb)
{
    int i = (blockIdx.x * 256 + threadIdx.x) * 4;
    float4 v = *(const float4*)(x + i);
    __nv_bfloat162 p0 = __floats2bfloat162_rn(v.x, v.y);
    __nv_bfloat162 p1 = __floats2bfloat162_rn(v.z, v.w);
    uint2 o = make_uint2(*(uint32_t*)&p0, *(uint32_t*)&p1);
    *(uint2*)(xb + i) = o;
}

// ---------------------------------------------------------------------------
// NT GEMM: C[M,N] = A[M,K] * B[N,K]^T, bf16 tensor core.
// BM=128, BN=128, BK=32, 256 threads, 8 warps (wm 0..1, wn 0..3),
// warp tile 64x32. 3-stage cp.async pipeline, ldmatrix fragment loads.
// smem: dynamic, 3*(128*40)*2 per operand = 61440 B total.
// EPI: 1 +bias for n>=512, 2 (acc - s[r]*u[r,n])/1024, 3 +x[r,n] fp32 out
// ---------------------------------------------------------------------------
#define NTSTG 5120   // elems per stage per operand (128*40)

template<int EPI, bool OUT_F32>
__global__ __launch_bounds__(256)
void gemm_nt(const __nv_bfloat16* __restrict__ A, int lda, long sA,
             const __nv_bfloat16* __restrict__ B, int ldb, long sB,
             void* __restrict__ Cp, int ldc, long sC, int K,
             const float* __restrict__ bias,
             const float* __restrict__ sdot, long sS,
             const __nv_bfloat16* __restrict__ U, int ldu, long sU,
             const float* __restrict__ Xres, int ldx, long sX)
{
    extern __shared__ __align__(16) __nv_bfloat16 sm[];
    __nv_bfloat16* Ab = sm;                 // 3 stages of [128][40]
    __nv_bfloat16* Bb = sm + 3 * NTSTG;     // 3 stages of [128][40]

    const int z = blockIdx.z;
    A += (size_t)z * sA;
    B += (size_t)z * sB;

    const int tid  = threadIdx.x;
    const int lane = tid & 31, warp = tid >> 5;
    const int wm = warp & 1, wn = warp >> 1;
    const int g = lane >> 2, t = lane & 3;
    const int row0 = blockIdx.y * 128, col0 = blockIdx.x * 128;

    const int lr = tid >> 1, lc = (tid & 1) * 16;   // stage loader: row, col

    // ldmatrix source offsets (element index within a stage)
    const int aoff = (wm * 64 + (lane & 15)) * 40 + ((lane >> 4) << 3);
    const int boff = (wn * 32 + (lane & 7) + ((lane >> 3) & 1) * 8) * 40
                   + ((lane >> 4) << 3);

    float acc[4][4][4] = {};
    const int kIters = K / 32;

    const __nv_bfloat16* aSrc = A + (size_t)(row0 + lr) * lda + lc;
    const __nv_bfloat16* bSrc = B + (size_t)(col0 + lr) * ldb + lc;

#pragma unroll
    for (int s = 0; s < 2; s++) {
        if (s < kIters) {
            __nv_bfloat16* as = Ab + s * NTSTG + lr * 40 + lc;
            __nv_bfloat16* bs = Bb + s * NTSTG + lr * 40 + lc;
            cp16(as,     aSrc + s * 32);
            cp16(as + 8, aSrc + s * 32 + 8);
            cp16(bs,     bSrc + s * 32);
            cp16(bs + 8, bSrc + s * 32 + 8);
        }
        cp_commit();
    }

    for (int it = 0; it < kIters; it++) {
        cp_wait1();
        __syncthreads();
        if (it + 2 < kIters) {
            const int st = (it + 2) % 3;
            __nv_bfloat16* as = Ab + st * NTSTG + lr * 40 + lc;
            __nv_bfloat16* bs = Bb + st * NTSTG + lr * 40 + lc;
            cp16(as,     aSrc + (it + 2) * 32);
            cp16(as + 8, aSrc + (it + 2) * 32 + 8);
            cp16(bs,     bSrc + (it + 2) * 32);
            cp16(bs + 8, bSrc + (it + 2) * 32 + 8);
        }
        cp_commit();

        const int st = it % 3;
        const __nv_bfloat16* As = Ab + st * NTSTG;
        const __nv_bfloat16* Bs = Bb + st * NTSTG;
#pragma unroll
        for (int kc = 0; kc < 2; kc++) {
            uint32_t a[4][4];
#pragma unroll
            for (int i = 0; i < 4; i++)
                ldm4(a[i], As + aoff + i * 16 * 40 + kc * 16);
            uint32_t bm[2][4];
#pragma unroll
            for (int jp = 0; jp < 2; jp++)
                ldm4(bm[jp], Bs + boff + jp * 16 * 40 + kc * 16);
            // b tile j: jp = j>>1; regs {m0,m2} for even j, {m1,m3} for odd j
#pragma unroll
            for (int j = 0; j < 4; j++) {
                const uint32_t b0 = bm[j >> 1][j & 1];
                const uint32_t b1 = bm[j >> 1][(j & 1) + 2];
#pragma unroll
                for (int i = 0; i < 4; i++)
                    mma_bf16(acc[i][j], a[i][0], a[i][1], a[i][2], a[i][3], b0, b1);
            }
        }
    }

    // ---- epilogue ----
    const float invN = 1.0f / 1024.0f;
    const float* sd           = (EPI == 2) ? sdot + (size_t)z * sS : nullptr;
    const __nv_bfloat16* Uz   = (EPI == 2) ? U + (size_t)z * sU : nullptr;
    const float* Xz           = (EPI == 3) ? Xres + (size_t)z * sX : nullptr;
    float*          Cf = OUT_F32 ? (float*)Cp + (size_t)z * sC : nullptr;
    __nv_bfloat16*  Cb = OUT_F32 ? nullptr : (__nv_bfloat16*)Cp + (size_t)z * sC;

#pragma unroll
    for (int i = 0; i < 4; i++) {
        const int rb = row0 + wm * 64 + i * 16 + g;   // rows rb, rb+8
#pragma unroll
        for (int j = 0; j < 4; j++) {
            const int c = col0 + wn * 32 + j * 8 + t * 2;
            float v00 = acc[i][j][0], v01 = acc[i][j][1];
            float v10 = acc[i][j][2], v11 = acc[i][j][3];
            if (EPI == 1) {
                if (c >= 512) {
                    float b0 = bias[c - 512], b1 = bias[c - 511];
                    v00 += b0; v01 += b1; v10 += b0; v11 += b1;
                }
            } else if (EPI == 2) {
                float s0 = sd[rb], s1 = sd[rb + 8];
                __nv_bfloat162 u0 = *(const __nv_bfloat162*)(Uz + (size_t)rb * ldu + c);
                __nv_bfloat162 u1 = *(const __nv_bfloat162*)(Uz + (size_t)(rb + 8) * ldu + c);
                float2 fu0 = __bfloat1622float2(u0);
                float2 fu1 = __bfloat1622float2(u1);
                v00 = (v00 - s0 * fu0.x) * invN;
                v01 = (v01 - s0 * fu0.y) * invN;
                v10 = (v10 - s1 * fu1.x) * invN;
                v11 = (v11 - s1 * fu1.y) * invN;
            } else if (EPI == 3) {
                float2 x0 = *(const float2*)(Xz + (size_t)rb * ldx + c);
                float2 x1 = *(const float2*)(Xz + (size_t)(rb + 8) * ldx + c);
                v00 += x0.x; v01 += x0.y; v10 += x1.x; v11 += x1.y;
            }
            if (OUT_F32) {
                *(float2*)(Cf + (size_t)rb * ldc + c)       = make_float2(v00, v01);
                *(float2*)(Cf + (size_t)(rb + 8) * ldc + c) = make_float2(v10, v11);
            } else {
                *(__nv_bfloat162*)(Cb + (size_t)rb * ldc + c)       = __floats2bfloat162_rn(v00, v01);
                *(__nv_bfloat162*)(Cb + (size_t)(rb + 8) * ldc + c) = __floats2bfloat162_rn(v10, v11);
            }
        }
    }
}

// ---------------------------------------------------------------------------
// TT GEMM (Mt = unary^T * beta per batch): operands stored [K][*].
// BM=64, BN=64, BK=32, 256 thr, warps 2m x 4n, ldmatrix.trans, 3-stage cp.async.
// ---------------------------------------------------------------------------
__global__ __launch_bounds__(256)
void gemm_tt(const __nv_bfloat16* __restrict__ A, int lda, long sA,
             const __nv_bfloat16* __restrict__ B, int ldb, long sB,
             __nv_bfloat16* __restrict__ C, int ldc, long sC, int K)
{
    const int z = blockIdx.z;
    A += (size_t)z * sA; B += (size_t)z * sB; C += (size_t)z * sC;

    __shared__ __align__(16) __nv_bfloat16 SA[3][32][72];
    __shared__ __align__(16) __nv_bfloat16 SB[3][32][72];

    const int tid = threadIdx.x, lane = tid & 31, warp = tid >> 5;
    const int wm = warp >> 2, wn = warp & 3;
    const int m0 = blockIdx.y * 64, n0 = blockIdx.x * 64;

    const int lr = tid >> 3, lc = (tid & 7) * 8;

    float acc[2][2][4] = {};

    const int arow = ((lane >> 4) << 3) + (lane & 7);
    const int acol = ((lane >> 3) & 1) << 3;
    const int brow = (((lane >> 3) & 1) << 3) + (lane & 7);

    const __nv_bfloat16* aSrc = A + (size_t)lr * lda + m0 + lc;
    const __nv_bfloat16* bSrc = B + (size_t)lr * ldb + n0 + lc;
    const int kIters = K / 32;

#pragma unroll
    for (int s = 0; s < 2; s++) {
        if (s < kIters) {
            cp16(&SA[s][lr][lc], aSrc + (size_t)(s * 32) * lda);
            cp16(&SB[s][lr][lc], bSrc + (size_t)(s * 32) * ldb);
        }
        cp_commit();
    }

    for (int it = 0; it < kIters; it++) {
        cp_wait1();
        __syncthreads();
        if (it + 2 < kIters) {
            const int st = (it + 2) % 3;
            cp16(&SA[st][lr][lc], aSrc + (size_t)((it + 2) * 32) * lda);
            cp16(&SB[st][lr][lc], bSrc + (size_t)((it + 2) * 32) * ldb);
        }
        cp_commit();

        const int st = it % 3;
#pragma unroll
        for (int kc = 0; kc < 2; kc++) {
            uint32_t a[2][4], b[2][2];
#pragma unroll
            for (int i = 0; i < 2; i++) {
                const int mb = wm * 32 + i * 16;
                uint32_t addr = smem_u32(&SA[st][kc * 16 + arow][mb + acol]);
                asm volatile(
                    "ldmatrix.sync.aligned.m8n8.x4.trans.shared.b16 {%0,%1,%2,%3},[%4];"
                    : "=r"(a[i][0]), "=r"(a[i][1]), "=r"(a[i][2]), "=r"(a[i][3])
                    : "r"(addr));
            }
#pragma unroll
            for (int j = 0; j < 2; j++) {
                const int nb = wn * 16 + j * 8;
                uint32_t addr = smem_u32(&SB[st][kc * 16 + brow][nb]);
                asm volatile(
                    "ldmatrix.sync.aligned.m8n8.x2.trans.shared.b16 {%0,%1},[%2];"
                    : "=r"(b[j][0]), "=r"(b[j][1])
                    : "r"(addr));
            }
#pragma unroll
            for (int i = 0; i < 2; i++)
#pragma unroll
                for (int j = 0; j < 2; j++)
                    mma_bf16(acc[i][j], a[i][0], a[i][1], a[i][2], a[i][3],
                             b[j][0], b[j][1]);
        }
    }

    const int g = lane >> 2, t = lane & 3;
#pragma unroll
    for (int i = 0; i < 2; i++) {
        const int rb = m0 + wm * 32 + i * 16 + g;
#pragma unroll
        for (int j = 0; j < 2; j++) {
            const int c = n0 + wn * 16 + j * 8 + t * 2;
            *(__nv_bfloat162*)(C + (size_t)rb * ldc + c)       = __floats2bfloat162_rn(acc[i][j][0], acc[i][j][1]);
            *(__nv_bfloat162*)(C + (size_t)(rb + 8) * ldc + c) = __floats2bfloat162_rn(acc[i][j][2], acc[i][j][3]);
        }
    }
}

// ---------------------------------------------------------------------------
__global__ __launch_bounds__(256)
void rowdot(const __nv_bfloat16* __restrict__ proj, float* __restrict__ s)
{
    const int row  = blockIdx.x * 8 + (threadIdx.x >> 5);
    const int lane = threadIdx.x & 31;
    const __nv_bfloat16* pa = proj + (size_t)row * PJ + lane * 8;
    uint4 va = *(const uint4*)pa;
    uint4 vb = *(const uint4*)(pa + FEAT);
    const __nv_bfloat162* ha = (const __nv_bfloat162*)&va;
    const __nv_bfloat162* hb = (const __nv_bfloat162*)&vb;
    float sum = 0.0f;
#pragma unroll
    for (int i = 0; i < 4; i++) {
        float2 fa = __bfloat1622float2(ha[i]);
        float2 fb = __bfloat1622float2(hb[i]);
        sum += fa.x * fb.x + fa.y * fb.y;
    }
#pragma unroll
    for (int o = 16; o > 0; o >>= 1)
        sum += __shfl_xor_sync(0xFFFFFFFFu, sum, o);
    if (lane == 0) s[row] = sum;
}

// ---------------------------------------------------------------------------
extern "C" void kernel_launch(void* const* d_in, const int* in_sizes, int n_in,
                              void* d_out, int out_size)
{
    const float* x  = (const float*)d_in[0];
    const float* Wa = (const float*)d_in[1];
    const float* Wb = (const float*)d_in[2];
    const float* Wu = (const float*)d_in[3];
    const float* bu = (const float*)d_in[4];
    const float* Wr = (const float*)d_in[5];
    float* out = (float*)d_out;

    __nv_bfloat16 *W, *Wr2, *xb, *proj, *Mt, *att;
    float* s;
    cudaGetSymbolAddress((void**)&W,    g_W);
    cudaGetSymbolAddress((void**)&Wr2,  g_Wr);
    cudaGetSymbolAddress((void**)&xb,   g_xb);
    cudaGetSymbolAddress((void**)&proj, g_proj);
    cudaGetSymbolAddress((void**)&Mt,   g_Mt);
    cudaGetSymbolAddress((void**)&att,  g_att);
    cudaGetSymbolAddress((void**)&s,    g_s);

    const int SMEM = 6 * NTSTG * 2;   // 61440 B
    cudaFuncSetAttribute(gemm_nt<1, false>, cudaFuncAttributeMaxDynamicSharedMemorySize, SMEM);
    cudaFuncSetAttribute(gemm_nt<2, false>, cudaFuncAttributeMaxDynamicSharedMemorySize, SMEM);
    cudaFuncSetAttribute(gemm_nt<3, true>,  cudaFuncAttributeMaxDynamicSharedMemorySize, SMEM);

    // 0) pack weights + convert x to bf16
    pack_weights<<<1024, 256>>>(Wa, Wb, Wu, Wr, W, Wr2);
    convert_x<<<ROWS * FEAT / 1024, 256>>>(x, xb);

    // 1) fused projections: proj = x @ [Wa|Wb|Wu]^T (+bias on unary cols)
    gemm_nt<1, false><<<dim3(PJ / 128, ROWS / 128, 1), 256, SMEM>>>(
        xb, FEAT, 0, W, FEAT, 0, proj, PJ, 0, FEAT,
        bu, nullptr, 0, nullptr, 0, 0, nullptr, 0, 0);

    // 2) s[r] = alpha_r . beta_r
    rowdot<<<ROWS / 8, 256>>>(proj, s);

    // 3) per-batch Mt[g,f] = sum_n unary[n,g] * beta[n,f]
    gemm_tt<<<dim3(FEAT / 64, FEAT / 64, BATCH), 256>>>(
        proj + 512, PJ, (long)SEQ * PJ,
        proj + 256, PJ, (long)SEQ * PJ,
        Mt, FEAT, (long)FEAT * FEAT, SEQ);

    // 4) per-batch att = (alpha @ Mt^T - s*unary) / 1024
    gemm_nt<2, false><<<dim3(FEAT / 128, SEQ / 128, BATCH), 256, SMEM>>>(
        proj, PJ, (long)SEQ * PJ,
        Mt, FEAT, (long)FEAT * FEAT,
        att, FEAT, (long)SEQ * FEAT, FEAT,
        nullptr, s, (long)SEQ, proj + 512, PJ, (long)SEQ * PJ, nullptr, 0, 0);

    // 5) out = att @ W_r^T + x  (fp32 out)
    gemm_nt<3, true><<<dim3(FEAT / 128, ROWS / 128, 1), 256, SMEM>>>(
        att, FEAT, 0, Wr2, FEAT, 0, out, FEAT, 0, FEAT,
        nullptr, nullptr, 0, nullptr, 0, 0, x, FEAT, 0);
}

// round 5
// speedup vs baseline: 4.5042x; 1.0243x over previous
#include <cuda_runtime.h>
#include <cuda_bf16.h>
#include <cstdint>

#define BATCH 16
#define SEQ   1024
#define FEAT  256
#define ROWS  (BATCH * SEQ)     // 16384
#define PJ    768               // 3 * FEAT (alpha | beta | uW)

// ---- scratch (__device__ globals; no allocation allowed) ----
__device__ __align__(16) __nv_bfloat16 g_W   [PJ * FEAT];       // Wa | Wb | Wur
__device__ __align__(16) __nv_bfloat16 g_Wub [FEAT * FEAT];     // W_u bf16 [g][f]
__device__ __align__(16) __nv_bfloat16 g_Wrt [FEAT * FEAT];     // W_r^T bf16 [g][h]
__device__ __align__(16) __nv_bfloat16 g_xb  [ROWS * FEAT];     // x in bf16
__device__ __align__(16) __nv_bfloat16 g_proj[ROWS * PJ];       // [r][alpha|beta|uW]
__device__ __align__(16) __nv_bfloat16 g_Mt  [BATCH * FEAT * FEAT]; // Mt2[h][f]
__device__ float g_s [ROWS];
__device__ float g_br[FEAT];

// ---------------------------------------------------------------------------
__device__ __forceinline__ uint32_t smem_u32(const void* p) {
    return (uint32_t)__cvta_generic_to_shared(p);
}
__device__ __forceinline__ void cp16(void* s, const void* g) {
    asm volatile("cp.async.ca.shared.global [%0], [%1], 16;\n"
                 :: "r"(smem_u32(s)), "l"(g));
}
__device__ __forceinline__ void cp_commit() {
    asm volatile("cp.async.commit_group;\n");
}
__device__ __forceinline__ void cp_wait1() {
    asm volatile("cp.async.wait_group 1;\n");
}
__device__ __forceinline__ void mma_bf16(float c[4],
        uint32_t a0, uint32_t a1, uint32_t a2, uint32_t a3,
        uint32_t b0, uint32_t b1) {
    asm volatile(
        "mma.sync.aligned.m16n8k16.row.col.f32.bf16.bf16.f32 "
        "{%0,%1,%2,%3},{%4,%5,%6,%7},{%8,%9},{%0,%1,%2,%3};"
        : "+f"(c[0]), "+f"(c[1]), "+f"(c[2]), "+f"(c[3])
        : "r"(a0), "r"(a1), "r"(a2), "r"(a3), "r"(b0), "r"(b1));
}
__device__ __forceinline__ void ldm4(uint32_t r[4], const void* p) {
    asm volatile(
        "ldmatrix.sync.aligned.m8n8.x4.shared.b16 {%0,%1,%2,%3},[%4];"
        : "=r"(r[0]), "=r"(r[1]), "=r"(r[2]), "=r"(r[3])
        : "r"(smem_u32(p)));
}

// ---------------------------------------------------------------------------
// prep: merged x->bf16 convert, weight pack/convert/transpose, br = W_r @ b.
// blocks [0,4096): convert x. [4096,5120): pack. block 5120: br.
// ---------------------------------------------------------------------------
__global__ __launch_bounds__(256)
void prep(const float* __restrict__ x,
          const float* __restrict__ Wa, const float* __restrict__ Wb,
          const float* __restrict__ Wu, const float* __restrict__ Wr,
          const float* __restrict__ bu,
          __nv_bfloat16* __restrict__ xb, __nv_bfloat16* __restrict__ W,
          __nv_bfloat16* __restrict__ Wub, __nv_bfloat16* __restrict__ Wrt,
          float* __restrict__ br)
{
    const int blk = blockIdx.x, tid = threadIdx.x;
    if (blk < 4096) {
        int i = (blk * 256 + tid) * 4;
        float4 v = *(const float4*)(x + i);
        __nv_bfloat162 p0 = __floats2bfloat162_rn(v.x, v.y);
        __nv_bfloat162 p1 = __floats2bfloat162_rn(v.z, v.w);
        uint2 o = make_uint2(*(uint32_t*)&p0, *(uint32_t*)&p1);
        *(uint2*)(xb + i) = o;
    } else if (blk < 5120) {
        int j = (blk - 4096) * 256 + tid;       // [0, 262144)
        int sel = j >> 16, off = j & 65535;
        if (sel == 0)      W[j]                 = __float2bfloat16(Wa[off]);
        else if (sel == 1) W[j]                 = __float2bfloat16(Wb[off]);
        else if (sel == 2) Wub[off]             = __float2bfloat16(Wu[off]);
        else {                                   // transpose W_r
            int h = off >> 8, g = off & 255;
            Wrt[g * FEAT + h] = __float2bfloat16(Wr[off]);
        }
    } else {
        // br[h] = sum_g Wr[h,g] * bu[g]
        __shared__ float bsh[FEAT];
        bsh[tid] = bu[tid];
        __syncthreads();
        const float* wr = Wr + (size_t)tid * FEAT;
        float acc = 0.0f;
#pragma unroll 8
        for (int g = 0; g < FEAT; g += 4) {
            float4 w = *(const float4*)(wr + g);
            acc += w.x * bsh[g] + w.y * bsh[g + 1]
                 + w.z * bsh[g + 2] + w.w * bsh[g + 3];
        }
        br[tid] = acc;
    }
}

// ---------------------------------------------------------------------------
// NT GEMM: C[M,N] = A[M,K] * B[N,K]^T, bf16 tensor core.
// BM=128, BN=128, BK=32, 256 threads, warp tile 64x32,
// 3-stage cp.async pipeline, ldmatrix fragment loads. smem dynamic 61440 B.
// EPI: 1 +bias[c-512] for c>=512 (proj),
//      4 (acc - s[r]*u[r,c])/1024 + x[r,c], fp32 out (final)
// ---------------------------------------------------------------------------
#define NTSTG 5120   // elems per stage per operand (128*40)

template<int EPI, bool OUT_F32>
__global__ __launch_bounds__(256)
void gemm_nt(const __nv_bfloat16* __restrict__ A, int lda, long sA,
             const __nv_bfloat16* __restrict__ B, int ldb, long sB,
             void* __restrict__ Cp, int ldc, long sC, int K,
             const float* __restrict__ bias,
             const float* __restrict__ sdot, long sS,
             const __nv_bfloat16* __restrict__ U, int ldu, long sU,
             const float* __restrict__ Xres, int ldx, long sX)
{
    extern __shared__ __align__(16) __nv_bfloat16 sm[];
    __nv_bfloat16* Ab = sm;
    __nv_bfloat16* Bb = sm + 3 * NTSTG;

    const int z = blockIdx.z;
    A += (size_t)z * sA;
    B += (size_t)z * sB;

    const int tid  = threadIdx.x;
    const int lane = tid & 31, warp = tid >> 5;
    const int wm = warp & 1, wn = warp >> 1;
    const int g = lane >> 2, t = lane & 3;
    const int row0 = blockIdx.y * 128, col0 = blockIdx.x * 128;

    const int lr = tid >> 1, lc = (tid & 1) * 16;

    const int aoff = (wm * 64 + (lane & 15)) * 40 + ((lane >> 4) << 3);
    const int boff = (wn * 32 + (lane & 7) + ((lane >> 3) & 1) * 8) * 40
                   + ((lane >> 4) << 3);

    float acc[4][4][4] = {};
    const int kIters = K / 32;

    const __nv_bfloat16* aSrc = A + (size_t)(row0 + lr) * lda + lc;
    const __nv_bfloat16* bSrc = B + (size_t)(col0 + lr) * ldb + lc;

#pragma unroll
    for (int s = 0; s < 2; s++) {
        if (s < kIters) {
            __nv_bfloat16* as = Ab + s * NTSTG + lr * 40 + lc;
            __nv_bfloat16* bs = Bb + s * NTSTG + lr * 40 + lc;
            cp16(as,     aSrc + s * 32);
            cp16(as + 8, aSrc + s * 32 + 8);
            cp16(bs,     bSrc + s * 32);
            cp16(bs + 8, bSrc + s * 32 + 8);
        }
        cp_commit();
    }

    for (int it = 0; it < kIters; it++) {
        cp_wait1();
        __syncthreads();
        if (it + 2 < kIters) {
            const int st = (it + 2) % 3;
            __nv_bfloat16* as = Ab + st * NTSTG + lr * 40 + lc;
            __nv_bfloat16* bs = Bb + st * NTSTG + lr * 40 + lc;
            cp16(as,     aSrc + (it + 2) * 32);
            cp16(as + 8, aSrc + (it + 2) * 32 + 8);
            cp16(bs,     bSrc + (it + 2) * 32);
            cp16(bs + 8, bSrc + (it + 2) * 32 + 8);
        }
        cp_commit();

        const int st = it % 3;
        const __nv_bfloat16* As = Ab + st * NTSTG;
        const __nv_bfloat16* Bs = Bb + st * NTSTG;
#pragma unroll
        for (int kc = 0; kc < 2; kc++) {
            uint32_t a[4][4];
#pragma unroll
            for (int i = 0; i < 4; i++)
                ldm4(a[i], As + aoff + i * 16 * 40 + kc * 16);
            uint32_t bm[2][4];
#pragma unroll
            for (int jp = 0; jp < 2; jp++)
                ldm4(bm[jp], Bs + boff + jp * 16 * 40 + kc * 16);
#pragma unroll
            for (int j = 0; j < 4; j++) {
                const uint32_t b0 = bm[j >> 1][j & 1];
                const uint32_t b1 = bm[j >> 1][(j & 1) + 2];
#pragma unroll
                for (int i = 0; i < 4; i++)
                    mma_bf16(acc[i][j], a[i][0], a[i][1], a[i][2], a[i][3], b0, b1);
            }
        }
    }

    // ---- epilogue ----
    const float invN = 1.0f / 1024.0f;
    const float* sd           = (EPI == 4) ? sdot + (size_t)z * sS : nullptr;
    const __nv_bfloat16* Uz   = (EPI == 4) ? U + (size_t)z * sU : nullptr;
    const float* Xz           = (EPI == 4) ? Xres + (size_t)z * sX : nullptr;
    float*          Cf = OUT_F32 ? (float*)Cp + (size_t)z * sC : nullptr;
    __nv_bfloat16*  Cb = OUT_F32 ? nullptr : (__nv_bfloat16*)Cp + (size_t)z * sC;

#pragma unroll
    for (int i = 0; i < 4; i++) {
        const int rb = row0 + wm * 64 + i * 16 + g;
#pragma unroll
        for (int j = 0; j < 4; j++) {
            const int c = col0 + wn * 32 + j * 8 + t * 2;
            float v00 = acc[i][j][0], v01 = acc[i][j][1];
            float v10 = acc[i][j][2], v11 = acc[i][j][3];
            if (EPI == 1) {
                if (c >= 512) {
                    float b0 = bias[c - 512], b1 = bias[c - 511];
                    v00 += b0; v01 += b1; v10 += b0; v11 += b1;
                }
            } else if (EPI == 4) {
                float s0 = sd[rb], s1 = sd[rb + 8];
                __nv_bfloat162 u0 = *(const __nv_bfloat162*)(Uz + (size_t)rb * ldu + c);
                __nv_bfloat162 u1 = *(const __nv_bfloat162*)(Uz + (size_t)(rb + 8) * ldu + c);
                float2 fu0 = __bfloat1622float2(u0);
                float2 fu1 = __bfloat1622float2(u1);
                float2 x0 = *(const float2*)(Xz + (size_t)rb * ldx + c);
                float2 x1 = *(const float2*)(Xz + (size_t)(rb + 8) * ldx + c);
                v00 = (v00 - s0 * fu0.x) * invN + x0.x;
                v01 = (v01 - s0 * fu0.y) * invN + x0.y;
                v10 = (v10 - s1 * fu1.x) * invN + x1.x;
                v11 = (v11 - s1 * fu1.y) * invN + x1.y;
            }
            if (OUT_F32) {
                *(float2*)(Cf + (size_t)rb * ldc + c)       = make_float2(v00, v01);
                *(float2*)(Cf + (size_t)(rb + 8) * ldc + c) = make_float2(v10, v11);
            } else {
                *(__nv_bfloat162*)(Cb + (size_t)rb * ldc + c)       = __floats2bfloat162_rn(v00, v01);
                *(__nv_bfloat162*)(Cb + (size_t)(rb + 8) * ldc + c) = __floats2bfloat162_rn(v10, v11);
            }
        }
    }
}

// ---------------------------------------------------------------------------
// TT GEMM: C[m,n] = sum_k A[k][m] * B[k][n], operands stored [K][*].
// BM=64, BN=64, BK=32, 256 thr, warps 2m x 4n, ldmatrix.trans, 3-stage cp.async.
// ---------------------------------------------------------------------------
__global__ __launch_bounds__(256)
void gemm_tt(const __nv_bfloat16* __restrict__ A, int lda, long sA,
             const __nv_bfloat16* __restrict__ B, int ldb, long sB,
             __nv_bfloat16* __restrict__ C, int ldc, long sC, int K)
{
    const int z = blockIdx.z;
    A += (size_t)z * sA; B += (size_t)z * sB; C += (size_t)z * sC;

    __shared__ __align__(16) __nv_bfloat16 SA[3][32][72];
    __shared__ __align__(16) __nv_bfloat16 SB[3][32][72];

    const int tid = threadIdx.x, lane = tid & 31, warp = tid >> 5;
    const int wm = warp >> 2, wn = warp & 3;
    const int m0 = blockIdx.y * 64, n0 = blockIdx.x * 64;

    const int lr = tid >> 3, lc = (tid & 7) * 8;

    float acc[2][2][4] = {};

    const int arow = ((lane >> 4) << 3) + (lane & 7);
    const int acol = ((lane >> 3) & 1) << 3;
    const int brow = (((lane >> 3) & 1) << 3) + (lane & 7);

    const __nv_bfloat16* aSrc = A + (size_t)lr * lda + m0 + lc;
    const __nv_bfloat16* bSrc = B + (size_t)lr * ldb + n0 + lc;
    const int kIters = K / 32;

#pragma unroll
    for (int s = 0; s < 2; s++) {
        if (s < kIters) {
            cp16(&SA[s][lr][lc], aSrc + (size_t)(s * 32) * lda);
            cp16(&SB[s][lr][lc], bSrc + (size_t)(s * 32) * ldb);
        }
        cp_commit();
    }

    for (int it = 0; it < kIters; it++) {
        cp_wait1();
        __syncthreads();
        if (it + 2 < kIters) {
            const int st = (it + 2) % 3;
            cp16(&SA[st][lr][lc], aSrc + (size_t)((it + 2) * 32) * lda);
            cp16(&SB[st][lr][lc], bSrc + (size_t)((it + 2) * 32) * ldb);
        }
        cp_commit();

        const int st = it % 3;
#pragma unroll
        for (int kc = 0; kc < 2; kc++) {
            uint32_t a[2][4], b[2][2];
#pragma unroll
            for (int i = 0; i < 2; i++) {
                const int mb = wm * 32 + i * 16;
                uint32_t addr = smem_u32(&SA[st][kc * 16 + arow][mb + acol]);
                asm volatile(
                    "ldmatrix.sync.aligned.m8n8.x4.trans.shared.b16 {%0,%1,%2,%3},[%4];"
                    : "=r"(a[i][0]), "=r"(a[i][1]), "=r"(a[i][2]), "=r"(a[i][3])
                    : "r"(addr));
            }
#pragma unroll
            for (int j = 0; j < 2; j++) {
                const int nb = wn * 16 + j * 8;
                uint32_t addr = smem_u32(&SB[st][kc * 16 + brow][nb]);
                asm volatile(
                    "ldmatrix.sync.aligned.m8n8.x2.trans.shared.b16 {%0,%1},[%2];"
                    : "=r"(b[j][0]), "=r"(b[j][1])
                    : "r"(addr));
            }
#pragma unroll
            for (int i = 0; i < 2; i++)
#pragma unroll
                for (int j = 0; j < 2; j++)
                    mma_bf16(acc[i][j], a[i][0], a[i][1], a[i][2], a[i][3],
                             b[j][0], b[j][1]);
        }
    }

    const int g = lane >> 2, t = lane & 3;
#pragma unroll
    for (int i = 0; i < 2; i++) {
        const int rb = m0 + wm * 32 + i * 16 + g;
#pragma unroll
        for (int j = 0; j < 2; j++) {
            const int c = n0 + wn * 16 + j * 8 + t * 2;
            *(__nv_bfloat162*)(C + (size_t)rb * ldc + c)       = __floats2bfloat162_rn(acc[i][j][0], acc[i][j][1]);
            *(__nv_bfloat162*)(C + (size_t)(rb + 8) * ldc + c) = __floats2bfloat162_rn(acc[i][j][2], acc[i][j][3]);
        }
    }
}

// ---------------------------------------------------------------------------
// rowdot: s[r] = dot(alpha[r,:], beta[r,:]). 2 rows per warp for ILP.
// ---------------------------------------------------------------------------
__global__ __launch_bounds__(256)
void rowdot(const __nv_bfloat16* __restrict__ proj, float* __restrict__ s)
{
    const int warp = threadIdx.x >> 5, lane = threadIdx.x & 31;
    const int row  = blockIdx.x * 16 + warp * 2;
    const __nv_bfloat16* p0 = proj + (size_t)row * PJ + lane * 8;
    const __nv_bfloat16* p1 = p0 + PJ;
    uint4 va0 = *(const uint4*)p0;
    uint4 vb0 = *(const uint4*)(p0 + FEAT);
    uint4 va1 = *(const uint4*)p1;
    uint4 vb1 = *(const uint4*)(p1 + FEAT);
    const __nv_bfloat162* ha0 = (const __nv_bfloat162*)&va0;
    const __nv_bfloat162* hb0 = (const __nv_bfloat162*)&vb0;
    const __nv_bfloat162* ha1 = (const __nv_bfloat162*)&va1;
    const __nv_bfloat162* hb1 = (const __nv_bfloat162*)&vb1;
    float s0 = 0.0f, s1 = 0.0f;
#pragma unroll
    for (int i = 0; i < 4; i++) {
        float2 a0 = __bfloat1622float2(ha0[i]);
        float2 b0 = __bfloat1622float2(hb0[i]);
        float2 a1 = __bfloat1622float2(ha1[i]);
        float2 b1 = __bfloat1622float2(hb1[i]);
        s0 += a0.x * b0.x + a0.y * b0.y;
        s1 += a1.x * b1.x + a1.y * b1.y;
    }
#pragma unroll
    for (int o = 16; o > 0; o >>= 1) {
        s0 += __shfl_xor_sync(0xFFFFFFFFu, s0, o);
        s1 += __shfl_xor_sync(0xFFFFFFFFu, s1, o);
    }
    if (lane == 0) { s[row] = s0; s[row + 1] = s1; }
}

// ---------------------------------------------------------------------------
extern "C" void kernel_launch(void* const* d_in, const int* in_sizes, int n_in,
                              void* d_out, int out_size)
{
    const float* x  = (const float*)d_in[0];
    const float* Wa = (const float*)d_in[1];
    const float* Wb = (const float*)d_in[2];
    const float* Wu = (const float*)d_in[3];
    const float* bu = (const float*)d_in[4];
    const float* Wr = (const float*)d_in[5];
    float* out = (float*)d_out;

    __nv_bfloat16 *W, *Wub, *Wrt, *xb, *proj, *Mt;
    float *s, *br;
    cudaGetSymbolAddress((void**)&W,    g_W);
    cudaGetSymbolAddress((void**)&Wub,  g_Wub);
    cudaGetSymbolAddress((void**)&Wrt,  g_Wrt);
    cudaGetSymbolAddress((void**)&xb,   g_xb);
    cudaGetSymbolAddress((void**)&proj, g_proj);
    cudaGetSymbolAddress((void**)&Mt,   g_Mt);
    cudaGetSymbolAddress((void**)&s,    g_s);
    cudaGetSymbolAddress((void**)&br,   g_br);

    const int SMEM = 6 * NTSTG * 2;   // 61440 B
    cudaFuncSetAttribute(gemm_nt<1, false>, cudaFuncAttributeMaxDynamicSharedMemorySize, SMEM);
    cudaFuncSetAttribute(gemm_nt<4, true>,  cudaFuncAttributeMaxDynamicSharedMemorySize, SMEM);

    // 0) prep: x->bf16, pack Wa/Wb, Wu->bf16, Wr^T->bf16, br = Wr@b
    prep<<<5121, 256>>>(x, Wa, Wb, Wu, Wr, bu, xb, W, Wub, Wrt, br);

    // 0b) Wur = W_r @ W_u  ->  third segment of packed W
    //     gemm_tt: C[h,f] = sum_g Wrt[g][h] * Wub[g][f]
    gemm_tt<<<dim3(FEAT / 64, FEAT / 64, 1), 256>>>(
        Wrt, FEAT, 0, Wub, FEAT, 0, W + 512 * FEAT, FEAT, 0, FEAT);

    // 1) proj = x @ [Wa|Wb|Wur]^T (+br on uW cols)
    gemm_nt<1, false><<<dim3(PJ / 128, ROWS / 128, 1), 256, SMEM>>>(
        xb, FEAT, 0, W, FEAT, 0, proj, PJ, 0, FEAT,
        br, nullptr, 0, nullptr, 0, 0, nullptr, 0, 0);

    // 2) s[r] = alpha_r . beta_r
    rowdot<<<ROWS / 16, 256>>>(proj, s);

    // 3) per-batch Mt2[h,f] = sum_n uW[n,h] * beta[n,f]
    gemm_tt<<<dim3(FEAT / 64, FEAT / 64, BATCH), 256>>>(
        proj + 512, PJ, (long)SEQ * PJ,
        proj + 256, PJ, (long)SEQ * PJ,
        Mt, FEAT, (long)FEAT * FEAT, SEQ);

    // 4) out = (alpha @ Mt2^T - s*uW)/1024 + x   (fp32 out, single pass)
    gemm_nt<4, true><<<dim3(FEAT / 128, SEQ / 128, BATCH), 256, SMEM>>>(
        proj, PJ, (long)SEQ * PJ,
        Mt, FEAT, (long)FEAT * FEAT,
        out, FEAT, (long)SEQ * FEAT, FEAT,
        nullptr, s, (long)SEQ, proj + 512, PJ, (long)SEQ * PJ,
        x, FEAT, (long)SEQ * FEAT);
}